// round 1
// baseline (speedup 1.0000x reference)
#include <cuda_runtime.h>
#include <math.h>

#define TT 8192
#define HH 512

// ---------------- scratch (allowed: __device__ globals) ----------------
__device__ float g_h1[(TT + 1) * HH];   // layer-1 hidden sequence, slot 0 = h0[0]
__device__ float g_h2[(TT + 1) * HH];   // layer-2 hidden sequence, slot 0 = h0[1]
__device__ int   g_cnt0[TT];            // completion counters for h1[t]
__device__ int   g_cnt1[TT];            // completion counters for h2[t]

// ---------------- sync primitives ----------------
__device__ __forceinline__ int ld_acq(const int* p) {
    int v;
    asm volatile("ld.acquire.gpu.global.b32 %0, [%1];" : "=r"(v) : "l"(p) : "memory");
    return v;
}
__device__ __forceinline__ void red_rel(int* p) {
    asm volatile("red.release.gpu.global.add.s32 [%0], %1;" :: "l"(p), "r"(1) : "memory");
}

__device__ __forceinline__ float sigmoidf_(float x) {
    return 1.0f / (1.0f + expf(-x));
}
__device__ __forceinline__ float logsigf_(float z) {
    // log(sigmoid(z)), numerically stable
    if (z >= 0.0f) return -log1pf(expf(-z));
    return z - log1pf(expf(z));
}

// ---------------- init: zero flags, seed h0 slots ----------------
__global__ void init_kernel(const float* __restrict__ h0) {
    int i = blockIdx.x * blockDim.x + threadIdx.x;
    if (i < TT) { g_cnt0[i] = 0; g_cnt1[i] = 0; }
    if (i < HH) {
        g_h1[i] = h0[i];
        g_h2[i] = h0[HH + i];
    }
}

// ---------------- persistent pipelined LSTM ----------------
// grid = 129 blocks x 256 threads.
//   blocks [0,64):   layer 1, each owns 8 hidden outputs
//   blocks [64,128): layer 2, each owns 8 hidden outputs (lags layer 1 by 1 step)
//   block 128:       head + BCE loss (lags layer 2)
// Per block: 64 weight rows (4 gates x 8 outputs for W_ih and W_hh) of K=512,
// held in registers: thread tt -> row (tt>>2), k-quarter g=(tt&3).
__global__ void __launch_bounds__(256, 1) lstm_kernel(
    const float* __restrict__ x,       // (T,1,H)
    const float* __restrict__ truth,   // (T,1,2)
    const float* __restrict__ c0,      // (2,1,H)
    const float* __restrict__ Wih0, const float* __restrict__ Whh0,
    const float* __restrict__ bih0, const float* __restrict__ bhh0,
    const float* __restrict__ Wih1, const float* __restrict__ Whh1,
    const float* __restrict__ bih1, const float* __restrict__ bhh1,
    const float* __restrict__ Whead, const float* __restrict__ bhead,
    float* __restrict__ out)
{
    const int b = blockIdx.x;

    // ================= HEAD + LOSS block =================
    if (b == 128) {
        const int l = threadIdx.x;
        if (l >= 32) return;
        float w0[16], w1[16];
#pragma unroll
        for (int i = 0; i < 16; i++) {
            w0[i] = Whead[i * 32 + l];
            w1[i] = Whead[HH + i * 32 + l];
        }
        const float bb0 = bhead[0], bb1 = bhead[1];
        double acc = 0.0;
        for (int t = 0; t < TT; t++) {
            if (l == 0) { while (ld_acq(&g_cnt1[t]) < 64) {} }
            __syncwarp();
            float s0 = 0.f, s1 = 0.f;
            const float* hrow = g_h2 + (long)(t + 1) * HH;
#pragma unroll
            for (int i = 0; i < 16; i++) {
                float hv = __ldcg(hrow + i * 32 + l);
                s0 += w0[i] * hv;
                s1 += w1[i] * hv;
            }
#pragma unroll
            for (int m = 16; m >= 1; m >>= 1) {
                s0 += __shfl_xor_sync(0xffffffffu, s0, m);
                s1 += __shfl_xor_sync(0xffffffffu, s1, m);
            }
            if (l == 0) {
                float z0 = s0 + bb0, z1 = s1 + bb1;
                float y0 = truth[t * 2 + 0], y1 = truth[t * 2 + 1];
                float t0 = y0 * fmaxf(logsigf_(z0), -100.0f)
                         + (1.0f - y0) * fmaxf(logsigf_(-z0), -100.0f);
                float t1 = y1 * fmaxf(logsigf_(z1), -100.0f)
                         + (1.0f - y1) * fmaxf(logsigf_(-z1), -100.0f);
                acc += (double)t0 + (double)t1;
            }
        }
        if (l == 0) out[0] = (float)(-acc / (double)(TT * 2));
        return;
    }

    // ================= LSTM layer blocks =================
    const int role = b >> 6;            // 0 = layer 1, 1 = layer 2
    const int j0   = (b & 63) * 8;      // first hidden output owned by this block
    const int tt   = threadIdx.x;
    const int rowLocal = tt >> 2;       // 0..63
    const int g        = tt & 3;        // k-quarter (128 wide)
    const int half     = rowLocal >> 5; // 0: W_ih rows, 1: W_hh rows
    const int r5       = rowLocal & 31;
    const int gate     = r5 >> 3;       // i,f,g,o
    const int jj       = r5 & 7;

    const float* Wbase = half ? (role ? Whh1 : Whh0) : (role ? Wih1 : Wih0);
    const long rowOff = (long)(gate * HH + j0 + jj) * HH;

    // load this thread's 128 weights into registers (bank-rotated order)
    float4 w[32];
#pragma unroll
    for (int i4 = 0; i4 < 32; i4++) {
        int k4 = (i4 + 2 * g) & 31;
        w[i4] = __ldg((const float4*)(Wbase + rowOff + g * 128 + k4 * 4));
    }

    // update threads (tt<8) hold bias sums and cell state
    float bsum0 = 0.f, bsum1 = 0.f, bsum2 = 0.f, bsum3 = 0.f;
    float c = 0.f;
    if (tt < 8) {
        const float* bi = role ? bih1 : bih0;
        const float* bh = role ? bhh1 : bhh0;
        bsum0 = bi[0 * HH + j0 + tt] + bh[0 * HH + j0 + tt];
        bsum1 = bi[1 * HH + j0 + tt] + bh[1 * HH + j0 + tt];
        bsum2 = bi[2 * HH + j0 + tt] + bh[2 * HH + j0 + tt];
        bsum3 = bi[3 * HH + j0 + tt] + bh[3 * HH + j0 + tt];
        c = c0[role * HH + j0 + tt];
    }

    __shared__ float vecA[HH];   // layer input vector  (x[t] or h1[t])
    __shared__ float vecB[HH];   // own previous hidden (h{role}[t-1])
    __shared__ float gsum[64];

    float* myOut = role ? g_h2 : g_h1;
    const float* prevBuf = role ? g_h2 : g_h1;
    int* myCnt = role ? g_cnt1 : g_cnt0;

    for (int t = 0; t < TT; t++) {
        // prefetch x[t] before the spin (layer 1 only; address is known early)
        float4 pref = make_float4(0.f, 0.f, 0.f, 0.f);
        if (role == 0 && tt < 128)
            pref = __ldg((const float4*)(x + (long)t * HH + tt * 4));

        if (tt == 0) {
            if (role == 1) { while (ld_acq(&g_cnt0[t]) < 64) {} }
            if (t > 0)     { while (ld_acq(&myCnt[t - 1]) < 64) {} }
        }
        __syncthreads();

        // stage vectors into SMEM
        if (tt < 128) {
            if (role == 0) {
                *(float4*)(vecA + tt * 4) = pref;
            } else {
                *(float4*)(vecA + tt * 4) =
                    __ldcg((const float4*)(g_h1 + (long)(t + 1) * HH + tt * 4));
            }
        } else {
            int u = tt - 128;
            *(float4*)(vecB + u * 4) =
                __ldcg((const float4*)(prevBuf + (long)t * HH + u * 4));
        }
        __syncthreads();

        // register-resident matvec: row dot over this thread's 128-wide k-slice
        const float* vec = half ? vecB : vecA;
        float acc = 0.f;
#pragma unroll
        for (int i4 = 0; i4 < 32; i4++) {
            int k4 = (i4 + 2 * g) & 31;
            float4 hv = *(const float4*)(vec + g * 128 + k4 * 4);
            acc += w[i4].x * hv.x;
            acc += w[i4].y * hv.y;
            acc += w[i4].z * hv.z;
            acc += w[i4].w * hv.w;
        }
        acc += __shfl_xor_sync(0xffffffffu, acc, 1);
        acc += __shfl_xor_sync(0xffffffffu, acc, 2);
        if (g == 0) gsum[rowLocal] = acc;
        __syncthreads();

        // gate math + cell update for the 8 owned outputs
        if (tt < 8) {
            float p0 = gsum[0 * 8 + tt] + gsum[32 + 0 * 8 + tt] + bsum0;
            float p1 = gsum[1 * 8 + tt] + gsum[32 + 1 * 8 + tt] + bsum1;
            float p2 = gsum[2 * 8 + tt] + gsum[32 + 2 * 8 + tt] + bsum2;
            float p3 = gsum[3 * 8 + tt] + gsum[32 + 3 * 8 + tt] + bsum3;
            float ig = sigmoidf_(p0);
            float fg = sigmoidf_(p1);
            float gg = tanhf(p2);
            float og = sigmoidf_(p3);
            c = fg * c + ig * gg;
            float h = og * tanhf(c);
            myOut[(long)(t + 1) * HH + j0 + tt] = h;
        }
        __syncthreads();
        if (tt == 0) red_rel(&myCnt[t]);
    }
}

extern "C" void kernel_launch(void* const* d_in, const int* in_sizes, int n_in,
                              void* d_out, int out_size) {
    const float* x     = (const float*)d_in[0];
    const float* truth = (const float*)d_in[1];
    const float* h0    = (const float*)d_in[2];
    const float* c0    = (const float*)d_in[3];
    const float* Wih0  = (const float*)d_in[4];
    const float* Whh0  = (const float*)d_in[5];
    const float* bih0  = (const float*)d_in[6];
    const float* bhh0  = (const float*)d_in[7];
    const float* Wih1  = (const float*)d_in[8];
    const float* Whh1  = (const float*)d_in[9];
    const float* bih1  = (const float*)d_in[10];
    const float* bhh1  = (const float*)d_in[11];
    const float* Whead = (const float*)d_in[12];
    const float* bhead = (const float*)d_in[13];
    float* out = (float*)d_out;

    init_kernel<<<32, 256>>>(h0);
    lstm_kernel<<<129, 256>>>(x, truth, c0,
                              Wih0, Whh0, bih0, bhh0,
                              Wih1, Whh1, bih1, bhh1,
                              Whead, bhead, out);
}